// round 5
// baseline (speedup 1.0000x reference)
#include <cuda_runtime.h>
#include <cuda_fp16.h>
#include <cstdint>

#define DI __device__ __forceinline__

// ---------------- problem constants ----------------
constexpr int BATCH   = 16384;
constexpr int INF     = 512;
constexpr int OUTF    = 512;
constexpr int NG      = 8;
constexpr int KTOT    = INF * NG;    // 4096
constexpr int KC      = 64;          // K per chunk (128B fp16 row)
constexpr int NCH     = KTOT / KC;   // 64 chunks
constexpr int MT      = 128;         // M tile per CTA
constexpr int NT      = 256;         // N tile per CTA
constexpr int CONS    = 256;         // consumer threads (8 warps)
constexpr int PROD    = 64;          // producer threads (2 warps)
constexpr int THREADS = CONS + PROD; // 320
constexpr int STAGES  = 3;

constexpr int A_BYTES     = 128 * 128;            // 16 KB
constexpr int B_BYTES     = 256 * 128;            // 32 KB
constexpr int STAGE_BYTES = A_BYTES + B_BYTES;    // 48 KB
constexpr int SMEM_DYN    = 1024 + STAGES * STAGE_BYTES;

// fp16 W transposed to [OUTF, KTOT], K contiguous
__device__ __half g_Wt[(size_t)OUTF * KTOT];

// ---------------- PTX helpers ----------------
DI uint32_t smem_u32(const void* p) {
    uint32_t a;
    asm("{ .reg .u64 t; cvta.to.shared.u64 t, %1; cvt.u32.u64 %0, t; }" : "=r"(a) : "l"(p));
    return a;
}

DI float ex2approx(float z) {
    float r;
    asm("ex2.approx.f32 %0, %1;" : "=f"(r) : "f"(z));
    return r;
}

DI uint32_t swz(uint32_t off) { return off ^ ((off >> 3) & 0x70u); }

DI void ldmx4(uint32_t* r, uint32_t addr) {
    asm volatile("ldmatrix.sync.aligned.m8n8.x4.shared.b16 {%0,%1,%2,%3}, [%4];"
                 : "=r"(r[0]), "=r"(r[1]), "=r"(r[2]), "=r"(r[3]) : "r"(addr));
}

DI void mma16816(float* c, const uint32_t* a, const uint32_t* b) {
    asm volatile(
        "mma.sync.aligned.m16n8k16.row.col.f32.f16.f16.f32 "
        "{%0,%1,%2,%3}, {%4,%5,%6,%7}, {%8,%9}, {%0,%1,%2,%3};"
        : "+f"(c[0]), "+f"(c[1]), "+f"(c[2]), "+f"(c[3])
        : "r"(a[0]), "r"(a[1]), "r"(a[2]), "r"(a[3]), "r"(b[0]), "r"(b[1]));
}

DI void cp_async16(uint32_t dst, const void* src) {
    asm volatile("cp.async.cg.shared.global [%0], [%1], 16;" :: "r"(dst), "l"(src) : "memory");
}
#define CP_COMMIT() asm volatile("cp.async.commit_group;" ::: "memory")
#define CP_WAIT0()  asm volatile("cp.async.wait_group 0;" ::: "memory")

#define MBARRIER_INIT(addr, cnt) \
    asm volatile("mbarrier.init.shared.b64 [%0], %1;" :: "r"((uint32_t)(addr)), "r"((uint32_t)(cnt)) : "memory")
#define MBARRIER_ARRIVE(addr) \
    asm volatile("mbarrier.arrive.shared.b64 _, [%0];" :: "r"((uint32_t)(addr)) : "memory")

#define MBARRIER_WAIT_PARITY(mbar_addr, phase) do { \
    uint32_t _mbar = (uint32_t)(mbar_addr); \
    uint32_t _par  = (uint32_t)(phase); \
    uint32_t _done; \
    asm volatile( \
        "{\n\t.reg .pred p;\n\t" \
        "mbarrier.try_wait.parity.acquire.cta.shared::cta.b64 p, [%1], %2;\n\t" \
        "selp.b32 %0, 1, 0, p;\n\t}" \
        : "=r"(_done) : "r"(_mbar), "r"(_par) : "memory"); \
    if (!_done) { \
        asm volatile( \
            "{\n\t.reg .pred P1;\n\t" \
            "WAIT_LOOP_%=:\n\t" \
            "mbarrier.try_wait.parity.acquire.cta.shared::cta.b64 P1, [%0], %1, 0x989680;\n\t" \
            "@P1 bra.uni WAIT_DONE_%=;\n\t" \
            "bra.uni WAIT_LOOP_%=;\n\t" \
            "WAIT_DONE_%=:\n\t}" \
            :: "r"(_mbar), "r"(_par) : "memory"); \
    } \
} while (0)

// ---------------- kernel 1: W[K,N] f32 -> Wt[N,K] fp16 ----------------
__global__ void wt_kernel(const float* __restrict__ W) {
    __shared__ float tile[32][33];
    int k0 = blockIdx.x * 32, n0 = blockIdx.y * 32;
    int tx = threadIdx.x, ty = threadIdx.y;
#pragma unroll
    for (int i = 0; i < 32; i += 8)
        tile[ty + i][tx] = W[(size_t)(k0 + ty + i) * OUTF + n0 + tx];
    __syncthreads();
#pragma unroll
    for (int i = 0; i < 32; i += 8)
        g_Wt[(size_t)(n0 + ty + i) * KTOT + k0 + tx] = __float2half_rn(tile[tx][ty + i]);
}

// ---------------- kernel 2: warp-specialized fused basis + mma.sync GEMM ----
__global__ void __launch_bounds__(THREADS, 1)
gk_kernel(const float* __restrict__ x, const float* __restrict__ grid,
          float* __restrict__ out)
{
    extern __shared__ char smem[];
    uint32_t sb = (smem_u32(smem) + 1023u) & ~1023u;

    int tid  = threadIdx.x;
    int lane = tid & 31;
    int wid  = tid >> 5;
    int Mtile = blockIdx.x;
    int Ntile = blockIdx.y;

    // barriers: full[s] at sb + s*16, empty[s] at sb + s*16 + 8
    uint32_t fullB[STAGES], emptyB[STAGES];
#pragma unroll
    for (int s = 0; s < STAGES; s++) {
        fullB[s]  = sb + s * 16;
        emptyB[s] = sb + s * 16 + 8;
    }
    uint32_t aBuf[STAGES], bBuf[STAGES];
#pragma unroll
    for (int s = 0; s < STAGES; s++) {
        aBuf[s] = sb + 1024 + s * STAGE_BYTES;
        bBuf[s] = aBuf[s] + A_BYTES;
    }

    if (tid == 0) {
#pragma unroll
        for (int s = 0; s < STAGES; s++) {
            MBARRIER_INIT(fullB[s], PROD);
            MBARRIER_INIT(emptyB[s], CONS);
        }
    }
    __syncthreads();

    if (wid >= 8) {
        // ================= PRODUCER (warps 8-9, 64 threads) =================
        int pt = tid - CONS;                       // 0..63
        float aco = 1.75f * 1.2011224087864498f;   // (1/h)*sqrt(log2 e), h=4/7
        float nb[8];
#pragma unroll
        for (int g = 0; g < 8; g++) nb[g] = -grid[g] * aco;

        const __half* wbase = g_Wt + (size_t)(Ntile * NT) * KTOT;
        const float*  xrow0 = x + (size_t)(Mtile * MT + 2 * pt) * INF;
        const float*  xrow1 = xrow0 + INF;

        int st = 0, ph = 1;
        for (int c = 0; c < NCH; c++) {
            MBARRIER_WAIT_PARITY(emptyB[st], ph);

            // ---- B tile: 256 rows x 128B via cp.async ----
            uint32_t bB = bBuf[st];
#pragma unroll
            for (int r = 0; r < 32; r++) {
                int idx = pt + PROD * r;           // 0..2047 16B units
                int n   = idx >> 3;
                int seg = idx & 7;
                uint32_t off = (uint32_t)(n * 128 + seg * 16);
                const void* g = (const void*)(wbase + (size_t)n * KTOT + c * KC + seg * 8);
                cp_async16(bB + swz(off), g);
            }
            CP_COMMIT();

            // ---- A tile: rows 2*pt, 2*pt+1; 64 basis values each ----
            uint32_t aB = aBuf[st];
#pragma unroll
            for (int rr = 0; rr < 2; rr++) {
                const float* xr = rr ? xrow1 : xrow0;
                int row = 2 * pt + rr;
                float4 xa = *reinterpret_cast<const float4*>(xr + c * 8);
                float4 xb = *reinterpret_cast<const float4*>(xr + c * 8 + 4);
                float xs[8] = {xa.x, xa.y, xa.z, xa.w, xb.x, xb.y, xb.z, xb.w};
#pragma unroll
                for (int j = 0; j < 8; j++) {
                    uint32_t pk[4];
#pragma unroll
                    for (int q = 0; q < 4; q++) {
                        float v0 = fmaf(xs[j], aco, nb[2 * q]);
                        float v1 = fmaf(xs[j], aco, nb[2 * q + 1]);
                        float e0 = ex2approx(-(v0 * v0));  // exp(-u^2)=2^(-(u*sqrt(log2 e))^2)
                        float e1 = ex2approx(-(v1 * v1));
                        __half2 h = __floats2half2_rn(e0, e1);
                        pk[q] = *reinterpret_cast<uint32_t*>(&h);
                    }
                    uint32_t off = (uint32_t)(row * 128 + j * 16);
                    asm volatile("st.shared.v4.b32 [%0], {%1, %2, %3, %4};"
                                 :: "r"(aB + swz(off)), "r"(pk[0]), "r"(pk[1]), "r"(pk[2]), "r"(pk[3])
                                 : "memory");
                }
            }

            CP_WAIT0();
            MBARRIER_ARRIVE(fullB[st]);
            if (++st == STAGES) { st = 0; ph ^= 1; }
        }
    } else {
        // ================= CONSUMER (warps 0-7) =================
        // 8 warps = 2(M) x 4(N); warp tile 64x64
        int wm = wid >> 2;
        int wn = wid & 3;

        uint32_t aOff[4], bOff[4];
#pragma unroll
        for (int mi = 0; mi < 4; mi++) {
            int row = wm * 64 + mi * 16 + (lane & 15);
            int u   = lane >> 4;
            aOff[mi] = swz((uint32_t)(row * 128 + u * 16));
        }
#pragma unroll
        for (int p = 0; p < 4; p++) {
            int row = wn * 64 + p * 16 + ((lane >> 4) & 1) * 8 + (lane & 7);
            int u   = (lane >> 3) & 1;
            bOff[p] = swz((uint32_t)(row * 128 + u * 16));
        }

        float acc[4][8][4];
#pragma unroll
        for (int mi = 0; mi < 4; mi++)
#pragma unroll
            for (int ni = 0; ni < 8; ni++)
#pragma unroll
                for (int q = 0; q < 4; q++) acc[mi][ni][q] = 0.0f;

        int st = 0, ph = 0;
        for (int c = 0; c < NCH; c++) {
            MBARRIER_WAIT_PARITY(fullB[st], ph);
            uint32_t aB = aBuf[st], bB = bBuf[st];
#pragma unroll
            for (int ks = 0; ks < 4; ks++) {
                uint32_t a[4][4];
#pragma unroll
                for (int mi = 0; mi < 4; mi++)
                    ldmx4(a[mi], aB + (aOff[mi] ^ (ks * 32)));
                uint32_t b[8][2];
#pragma unroll
                for (int p = 0; p < 4; p++) {
                    uint32_t r[4];
                    ldmx4(r, bB + (bOff[p] ^ (ks * 32)));
                    b[2 * p][0] = r[0]; b[2 * p][1] = r[1];
                    b[2 * p + 1][0] = r[2]; b[2 * p + 1][1] = r[3];
                }
#pragma unroll
                for (int ni = 0; ni < 8; ni++)
#pragma unroll
                    for (int mi = 0; mi < 4; mi++)
                        mma16816(acc[mi][ni], a[mi], b[ni]);
            }
            MBARRIER_ARRIVE(emptyB[st]);
            if (++st == STAGES) { st = 0; ph ^= 1; }
        }

        // epilogue: direct f32 stores
        float* obase = out + (size_t)(Mtile * MT + wm * 64) * OUTF + Ntile * NT + wn * 64;
#pragma unroll
        for (int mi = 0; mi < 4; mi++) {
            int r0 = mi * 16 + (lane >> 2);
#pragma unroll
            for (int ni = 0; ni < 8; ni++) {
                int cl = ni * 8 + (lane & 3) * 2;
                float2 v0 = make_float2(acc[mi][ni][0], acc[mi][ni][1]);
                float2 v1 = make_float2(acc[mi][ni][2], acc[mi][ni][3]);
                *reinterpret_cast<float2*>(obase + (size_t)r0 * OUTF + cl) = v0;
                *reinterpret_cast<float2*>(obase + (size_t)(r0 + 8) * OUTF + cl) = v1;
            }
        }
    }
}

// ---------------- launch ----------------
extern "C" void kernel_launch(void* const* d_in, const int* in_sizes, int n_in,
                              void* d_out, int out_size) {
    const float* x    = (const float*)d_in[0];
    const float* grid = (const float*)d_in[1];
    const float* W    = (const float*)d_in[2];
    float* out = (float*)d_out;

    cudaFuncSetAttribute(gk_kernel, cudaFuncAttributeMaxDynamicSharedMemorySize, SMEM_DYN);

    dim3 tb(32, 8);
    wt_kernel<<<dim3(KTOT / 32, OUTF / 32), tb>>>(W);
    gk_kernel<<<dim3(BATCH / MT, OUTF / NT), THREADS, SMEM_DYN>>>(x, grid, out);
}

// round 6
// speedup vs baseline: 1.1106x; 1.1106x over previous
#include <cuda_runtime.h>
#include <cuda_fp16.h>
#include <cstdint>

#define DI __device__ __forceinline__

// ---------------- problem constants ----------------
constexpr int BATCH   = 16384;
constexpr int INF     = 512;
constexpr int OUTF    = 512;
constexpr int NG      = 8;
constexpr int KTOT    = INF * NG;    // 4096
constexpr int KC      = 64;          // K per chunk (128B fp16 row)
constexpr int NCH     = KTOT / KC;   // 64 chunks
constexpr int MT      = 128;         // M tile per CTA
constexpr int NT      = 256;         // N tile per CTA
constexpr int THREADS = 256;
constexpr int STAGES  = 3;

constexpr int A_BYTES     = 128 * 128;            // 16 KB
constexpr int B_BYTES     = 256 * 128;            // 32 KB
constexpr int STAGE_BYTES = A_BYTES + B_BYTES;    // 48 KB
constexpr int SMEM_DYN    = STAGES * STAGE_BYTES + 1024;

// fp16 W transposed to [OUTF, KTOT], K contiguous
__device__ __half g_Wt[(size_t)OUTF * KTOT];

// ---------------- PTX helpers ----------------
DI uint32_t smem_u32(const void* p) {
    uint32_t a;
    asm("{ .reg .u64 t; cvta.to.shared.u64 t, %1; cvt.u32.u64 %0, t; }" : "=r"(a) : "l"(p));
    return a;
}

// pack (lo,hi) fp32 -> f16x2 and take 2^x on both halves in one MUFU op
DI uint32_t ex2_f16x2(float lo, float hi) {
    uint32_t d;
    asm("{ .reg .b32 t; cvt.rn.f16x2.f32 t, %1, %2; ex2.approx.f16x2 %0, t; }"
        : "=r"(d) : "f"(hi), "f"(lo));
    return d;
}

DI uint32_t swz(uint32_t off) { return off ^ ((off >> 3) & 0x70u); }

DI void ldmx4(uint32_t* r, uint32_t addr) {
    asm volatile("ldmatrix.sync.aligned.m8n8.x4.shared.b16 {%0,%1,%2,%3}, [%4];"
                 : "=r"(r[0]), "=r"(r[1]), "=r"(r[2]), "=r"(r[3]) : "r"(addr));
}

DI void mma16816(float* c, const uint32_t* a, const uint32_t* b) {
    asm volatile(
        "mma.sync.aligned.m16n8k16.row.col.f32.f16.f16.f32 "
        "{%0,%1,%2,%3}, {%4,%5,%6,%7}, {%8,%9}, {%0,%1,%2,%3};"
        : "+f"(c[0]), "+f"(c[1]), "+f"(c[2]), "+f"(c[3])
        : "r"(a[0]), "r"(a[1]), "r"(a[2]), "r"(a[3]), "r"(b[0]), "r"(b[1]));
}

DI void cp_async16(uint32_t dst, const void* src) {
    asm volatile("cp.async.cg.shared.global [%0], [%1], 16;" :: "r"(dst), "l"(src) : "memory");
}
#define CP_COMMIT() asm volatile("cp.async.commit_group;" ::: "memory")
#define CP_WAIT1()  asm volatile("cp.async.wait_group 1;" ::: "memory")

// ---------------- kernel 1: W[K,N] f32 -> Wt[N,K] fp16 ----------------
__global__ void wt_kernel(const float* __restrict__ W) {
    __shared__ float tile[32][33];
    int k0 = blockIdx.x * 32, n0 = blockIdx.y * 32;
    int tx = threadIdx.x, ty = threadIdx.y;
#pragma unroll
    for (int i = 0; i < 32; i += 8)
        tile[ty + i][tx] = W[(size_t)(k0 + ty + i) * OUTF + n0 + tx];
    __syncthreads();
#pragma unroll
    for (int i = 0; i < 32; i += 8)
        g_Wt[(size_t)(n0 + ty + i) * KTOT + k0 + tx] = __float2half_rn(tile[tx][ty + i]);
}

// ---------------- kernel 2: fused basis + mma.sync GEMM ----------------
struct Ctx {
    float aco;
    float nb[8];
    const float* xthr;      // this thread's x slice (row m, feature offset half*4)
    const __half* wbase;    // Wt + Ntile*NT*KTOT
    int tid, m, half;
};

// B slice: 2 of 8 cp.async iterations (512B of the 32KB tile per thread-slice)
DI void produce_B_slice(const Ctx& ctx, int c, uint32_t bBase, int sl) {
#pragma unroll
    for (int r = 2 * sl; r < 2 * sl + 2; r++) {
        int idx = ctx.tid + THREADS * r;      // 0..2047 16B units
        int n   = idx >> 3;                   // local out-feature row (0..255)
        int seg = idx & 7;                    // 16B segment within 128B row
        uint32_t off = (uint32_t)(n * 128 + seg * 16);
        const void* g = (const void*)(ctx.wbase + (size_t)n * KTOT + c * KC + seg * 8);
        cp_async16(bBase + swz(off), g);
    }
}

// A slice: one feature (gi = sl) -> 8 gaussian values -> one 16B store
DI void produce_A_slice(const Ctx& ctx, uint32_t aBase, float xf, int sl) {
    uint32_t pk[4];
#pragma unroll
    for (int q = 0; q < 4; q++) {
        float v0 = fmaf(xf, ctx.aco, ctx.nb[2 * q]);
        float v1 = fmaf(xf, ctx.aco, ctx.nb[2 * q + 1]);
        // exp(-u^2) = 2^(-(u*sqrt(log2 e))^2); both halves in one MUFU
        pk[q] = ex2_f16x2(-(v0 * v0), -(v1 * v1));
    }
    uint32_t off = (uint32_t)(ctx.m * 128 + (ctx.half * 4 + sl) * 16);
    asm volatile("st.shared.v4.b32 [%0], {%1, %2, %3, %4};"
                 :: "r"(aBase + swz(off)), "r"(pk[0]), "r"(pk[1]), "r"(pk[2]), "r"(pk[3])
                 : "memory");
}

__global__ void __launch_bounds__(THREADS, 1)
gk_kernel(const float* __restrict__ x, const float* __restrict__ grid,
          float* __restrict__ out)
{
    extern __shared__ char smem[];
    uint32_t sb = (smem_u32(smem) + 1023u) & ~1023u;

    int tid  = threadIdx.x;
    int lane = tid & 31;
    int wid  = tid >> 5;
    int Mtile = blockIdx.x;
    int Ntile = blockIdx.y;

    Ctx ctx;
    ctx.aco = 1.75f * 1.2011224087864498f;   // (1/h)*sqrt(log2 e), h = 4/7
#pragma unroll
    for (int g = 0; g < 8; g++) ctx.nb[g] = -grid[g] * ctx.aco;
    ctx.tid   = tid;
    ctx.m     = tid >> 1;
    ctx.half  = tid & 1;
    ctx.xthr  = x + (size_t)(Mtile * MT + ctx.m) * INF + ctx.half * 4;
    ctx.wbase = g_Wt + (size_t)(Ntile * NT) * KTOT;

    uint32_t aBuf[STAGES], bBuf[STAGES];
#pragma unroll
    for (int s = 0; s < STAGES; s++) {
        aBuf[s] = sb + s * STAGE_BYTES;
        bBuf[s] = aBuf[s] + A_BYTES;
    }

    // warp tiling: 8 warps = 2(M) x 4(N); warp tile 64x64
    int wm = wid >> 2;
    int wn = wid & 3;

    uint32_t aOff[4], bOff[4];
#pragma unroll
    for (int mi = 0; mi < 4; mi++) {
        int row = wm * 64 + mi * 16 + (lane & 15);
        int u   = lane >> 4;
        aOff[mi] = swz((uint32_t)(row * 128 + u * 16));
    }
#pragma unroll
    for (int p = 0; p < 4; p++) {
        int row = wn * 64 + p * 16 + ((lane >> 4) & 1) * 8 + (lane & 7);
        int u   = (lane >> 3) & 1;
        bOff[p] = swz((uint32_t)(row * 128 + u * 16));
    }

    float acc[4][8][4];
#pragma unroll
    for (int mi = 0; mi < 4; mi++)
#pragma unroll
        for (int ni = 0; ni < 8; ni++)
#pragma unroll
            for (int q = 0; q < 4; q++) acc[mi][ni][q] = 0.0f;

    // prologue: fully stage chunks 0 and 1
    {
        float4 x0 = *reinterpret_cast<const float4*>(ctx.xthr + 0 * NG);
#pragma unroll
        for (int sl = 0; sl < 4; sl++) {
            produce_B_slice(ctx, 0, bBuf[0], sl);
            float xf = sl == 0 ? x0.x : sl == 1 ? x0.y : sl == 2 ? x0.z : x0.w;
            produce_A_slice(ctx, aBuf[0], xf, sl);
        }
        CP_COMMIT();
        float4 x1 = *reinterpret_cast<const float4*>(ctx.xthr + 1 * NG);
#pragma unroll
        for (int sl = 0; sl < 4; sl++) {
            produce_B_slice(ctx, 1, bBuf[1], sl);
            float xf = sl == 0 ? x1.x : sl == 1 ? x1.y : sl == 2 ? x1.z : x1.w;
            produce_A_slice(ctx, aBuf[1], xf, sl);
        }
        CP_COMMIT();
    }

    int s_cons = 0, s_prod = 2;

    for (int c = 0; c < NCH; c++) {
        CP_WAIT1();
        __syncthreads();

        bool doprod = (c + 2 < NCH);
        float4 xnext = make_float4(0.f, 0.f, 0.f, 0.f);
        if (doprod)
            xnext = *reinterpret_cast<const float4*>(ctx.xthr + (c + 2) * NG);

        uint32_t aB = aBuf[s_cons], bB = bBuf[s_cons];
        uint32_t aP = aBuf[s_prod], bP = bBuf[s_prod];

#pragma unroll
        for (int ks = 0; ks < 4; ks++) {
            uint32_t a[4][4];
#pragma unroll
            for (int mi = 0; mi < 4; mi++)
                ldmx4(a[mi], aB + (aOff[mi] ^ (ks * 32)));
            uint32_t b[8][2];
#pragma unroll
            for (int p = 0; p < 4; p++) {
                uint32_t r[4];
                ldmx4(r, bB + (bOff[p] ^ (ks * 32)));
                b[2 * p][0] = r[0]; b[2 * p][1] = r[1];
                b[2 * p + 1][0] = r[2]; b[2 * p + 1][1] = r[3];
            }

            // production slice for chunk c+2, issued into the tensor-pipe shadow
            if (doprod) {
                produce_B_slice(ctx, c + 2, bP, ks);
                float xf = ks == 0 ? xnext.x : ks == 1 ? xnext.y : ks == 2 ? xnext.z : xnext.w;
                produce_A_slice(ctx, aP, xf, ks);
            }

#pragma unroll
            for (int ni = 0; ni < 8; ni++)
#pragma unroll
                for (int mi = 0; mi < 4; mi++)
                    mma16816(acc[mi][ni], a[mi], b[ni]);
        }

        if (doprod) CP_COMMIT();

        if (++s_cons == STAGES) s_cons = 0;
        if (++s_prod == STAGES) s_prod = 0;
    }

    // epilogue: direct f32 stores from accumulators
    float* obase = out + (size_t)(Mtile * MT + wm * 64) * OUTF + Ntile * NT + wn * 64;
#pragma unroll
    for (int mi = 0; mi < 4; mi++) {
        int r0 = mi * 16 + (lane >> 2);
#pragma unroll
        for (int ni = 0; ni < 8; ni++) {
            int cl = ni * 8 + (lane & 3) * 2;
            float2 v0 = make_float2(acc[mi][ni][0], acc[mi][ni][1]);
            float2 v1 = make_float2(acc[mi][ni][2], acc[mi][ni][3]);
            *reinterpret_cast<float2*>(obase + (size_t)r0 * OUTF + cl) = v0;
            *reinterpret_cast<float2*>(obase + (size_t)(r0 + 8) * OUTF + cl) = v1;
        }
    }
}

// ---------------- launch ----------------
extern "C" void kernel_launch(void* const* d_in, const int* in_sizes, int n_in,
                              void* d_out, int out_size) {
    const float* x    = (const float*)d_in[0];
    const float* grid = (const float*)d_in[1];
    const float* W    = (const float*)d_in[2];
    float* out = (float*)d_out;

    cudaFuncSetAttribute(gk_kernel, cudaFuncAttributeMaxDynamicSharedMemorySize, SMEM_DYN);

    dim3 tb(32, 8);
    wt_kernel<<<dim3(KTOT / 32, OUTF / 32), tb>>>(W);
    gk_kernel<<<dim3(BATCH / MT, OUTF / NT), THREADS, SMEM_DYN>>>(x, grid, out);
}